// round 9
// baseline (speedup 1.0000x reference)
#include <cuda_runtime.h>
#include <math.h>

#define FULL 0xFFFFFFFFu
typedef unsigned long long u64;

// ---- packed f32x2 helpers (sm_103a) ------------------------------------
__device__ __forceinline__ u64 pk2(float lo, float hi) {
    u64 r; asm("mov.b64 %0, {%1, %2};" : "=l"(r) : "f"(lo), "f"(hi)); return r;
}
__device__ __forceinline__ float lo2(u64 x) { return __uint_as_float((unsigned)x); }
__device__ __forceinline__ float hi2(u64 x) { return __uint_as_float((unsigned)(x >> 32)); }
__device__ __forceinline__ u64 fma2(u64 a, u64 b, u64 c) {
    u64 d; asm("fma.rn.f32x2 %0, %1, %2, %3;" : "=l"(d) : "l"(a), "l"(b), "l"(c)); return d;
}
__device__ __forceinline__ u64 mul2(u64 a, u64 b) {
    u64 d; asm("mul.rn.f32x2 %0, %1, %2;" : "=l"(d) : "l"(a), "l"(b)); return d;
}
__device__ __forceinline__ u64 add2(u64 a, u64 b) {
    u64 d; asm("add.rn.f32x2 %0, %1, %2;" : "=l"(d) : "l"(a), "l"(b)); return d;
}
__device__ __forceinline__ u64 shfl64x(u64 x, int mask) {
    unsigned lo = (unsigned)x, hi = (unsigned)(x >> 32);
    lo = __shfl_xor_sync(FULL, lo, mask);
    hi = __shfl_xor_sync(FULL, hi, mask);
    return ((u64)hi << 32) | (u64)lo;
}
__device__ __forceinline__ float red2(u64 a, u64 b, u64 c, u64 d) {
    u64 s = add2(add2(a, b), add2(c, d));
    return lo2(s) + hi2(s);
}

// Exchange-row pitch in floats. pitch/4 = 17 (odd) -> the 8 lanes of each
// 128-bit access phase hit distinct 16B bank groups: conflict-free for the
// identity write AND every ring-permutation read used by the tournament.
#define EXP 68

// One warp per 64x64 SPD matrix. Lane k holds two columns (u, v) packed as
// 32 x f32x2. One-sided Jacobi, recursive-halving tournament. The V ring
// exchange goes through shared memory with 128-bit STS/LDS (16+16 MIO
// instrs) instead of 64 SHFLs: the shuffle unit was measured ~60% busy and
// was the contended pipe. Next-pairing dot fused into the LDS loop.
// Sweeps 0-5 ballot-free; 6+ ballot-gated skip rounds + early exit.
// Cap 16 sweeps (10 measured insufficient). __launch_bounds__(32,12):
// (32,13) measured catastrophic (ptxas spills U/V, 4x slowdown).
__global__ __launch_bounds__(32, 12) void logeig_jacobi(const float* __restrict__ P,
                                                        float* __restrict__ X,
                                                        int nmat) {
    const int m = blockIdx.x;
    if (m >= nmat) return;
    const int k = threadIdx.x;
    const float* __restrict__ Pm = P + (size_t)m * 4096;
    float* __restrict__ Xm = X + (size_t)m * 4096;

    // One pool, two lives: mainloop exchange rows [32][EXP], epilogue W[64][66].
    __shared__ __align__(16) float POOL[64 * 66];
    __shared__ float gw[64];
    float (*EX)[EXP] = (float (*)[EXP])POOL;

    u64 U[32], V[32];
#pragma unroll
    for (int j = 0; j < 32; ++j) {
        U[j] = pk2(Pm[(2 * j) * 64 + k],        Pm[(2 * j + 1) * 64 + k]);
        V[j] = pk2(Pm[(2 * j) * 64 + (k + 32)], Pm[(2 * j + 1) * 64 + (k + 32)]);
    }

    float du = 0.f, dv = 0.f;

    for (int sweep = 0; sweep < 16; ++sweep) {
        const bool gated = (sweep >= 6);

        // exact norms at sweep start
        {
            u64 a0 = 0, a1 = 0, b0 = 0, b1 = 0;
#pragma unroll
            for (int j = 0; j < 32; j += 2) {
                a0 = fma2(U[j], U[j], a0);     a1 = fma2(U[j + 1], U[j + 1], a1);
                b0 = fma2(V[j], V[j], b0);     b1 = fma2(V[j + 1], V[j + 1], b1);
            }
            u64 a = add2(a0, a1), b = add2(b0, b1);
            du = lo2(a) + hi2(a);
            dv = lo2(b) + hi2(b);
        }

        unsigned any = 0u;
        for (int g = 32; g >= 1; g >>= 1) {
            const int src = (k & ~(g - 1)) | ((k + 1) & (g - 1));

            // fresh dot at level start
            float x;
            {
                u64 x0 = 0, x1 = 0, x2 = 0, x3 = 0;
#pragma unroll
                for (int j = 0; j < 32; j += 4) {
                    x0 = fma2(U[j],     V[j],     x0);
                    x1 = fma2(U[j + 1], V[j + 1], x1);
                    x2 = fma2(U[j + 2], V[j + 2], x2);
                    x3 = fma2(U[j + 3], V[j + 3], x3);
                }
                x = red2(x0, x1, x2, x3);
            }

            for (int r = 0; r < g; ++r) {
                bool rot = (x * x > 1e-8f * du * dv);
                unsigned bal;
                if (gated) {
                    bal = __ballot_sync(FULL, rot);
                    any |= bal;
                } else {
                    bal = FULL;
                }

                if (bal) {
                    // one-division angle, rotate u and v in place
                    float a = dv - du;
                    float b = 2.0f * x;
                    float D = sqrtf(fmaf(a, a, b * b));
                    float t = __fdividef(b, a + copysignf(D, a));
                    if (!rot) t = 0.0f;
                    float c = rsqrtf(fmaf(t, t, 1.0f));
                    float s = t * c;

                    float ndu = fmaf(-t, x, du);
                    float ndv = fmaf( t, x, dv);

                    u64 cc = pk2(c, c), ss = pk2(s, s), ns = pk2(-s, -s);
#pragma unroll
                    for (int j = 0; j < 32; ++j) {
                        u64 un = fma2(cc, U[j], mul2(ns, V[j]));
                        u64 vn = fma2(cc, V[j], mul2(ss, U[j]));
                        U[j] = un;
                        V[j] = vn;
                    }
                    du = ndu;
                    dv = ndv;
                }

                // V ring exchange via shared (128-bit), dot fused into loads
                {
                    ulonglong2* wr = (ulonglong2*)&EX[k][0];
#pragma unroll
                    for (int t2 = 0; t2 < 16; ++t2) {
                        ulonglong2 w; w.x = V[2 * t2]; w.y = V[2 * t2 + 1];
                        wr[t2] = w;
                    }
                }
                __syncwarp();
                {
                    const ulonglong2* rd = (const ulonglong2*)&EX[src][0];
                    u64 x0 = 0, x1 = 0, x2 = 0, x3 = 0;
#pragma unroll
                    for (int t2 = 0; t2 < 16; ++t2) {
                        ulonglong2 w = rd[t2];
                        V[2 * t2]     = w.x;
                        V[2 * t2 + 1] = w.y;
                        if (t2 & 1) {
                            x2 = fma2(U[2 * t2],     w.x, x2);
                            x3 = fma2(U[2 * t2 + 1], w.y, x3);
                        } else {
                            x0 = fma2(U[2 * t2],     w.x, x0);
                            x1 = fma2(U[2 * t2 + 1], w.y, x1);
                        }
                    }
                    x = red2(x0, x1, x2, x3);
                }
                __syncwarp();
                dv = __shfl_sync(FULL, dv, src);
            }

            // split: lower half-lanes keep u-set, upper keep v-set
            if (g > 1) {
                const int h = g >> 1;
                const bool low = (k & h) == 0;
#pragma unroll
                for (int j = 0; j < 32; ++j) {
                    u64 pu = shfl64x(U[j], h);
                    u64 pv = shfl64x(V[j], h);
                    if (low) V[j] = pu; else U[j] = pv;
                }
                float pdu = __shfl_xor_sync(FULL, du, h);
                float pdv = __shfl_xor_sync(FULL, dv, h);
                if (low) dv = pdu; else du = pdv;
            }
        }
        if (gated && any == 0u) break;
    }

    // exact final norms -> log weights  g_p = 0.5*log(d_p)/d_p
    float fdu, fdv;
    {
        u64 a0 = 0, a1 = 0, b0 = 0, b1 = 0;
#pragma unroll
        for (int j = 0; j < 32; j += 2) {
            a0 = fma2(U[j], U[j], a0);     a1 = fma2(U[j + 1], U[j + 1], a1);
            b0 = fma2(V[j], V[j], b0);     b1 = fma2(V[j + 1], V[j + 1], b1);
        }
        u64 a = add2(a0, a1), b = add2(b0, b1);
        fdu = lo2(a) + hi2(a);
        fdv = lo2(b) + hi2(b);
    }

    __syncwarp();                       // mainloop reads of POOL are done
    float (*W)[66] = (float (*)[66])POOL;
#pragma unroll
    for (int j = 0; j < 32; ++j) {
        W[k][2 * j]          = lo2(U[j]);
        W[k][2 * j + 1]      = hi2(U[j]);
        W[k + 32][2 * j]     = lo2(V[j]);
        W[k + 32][2 * j + 1] = hi2(V[j]);
    }
    gw[k]      = 0.5f * __logf(fdu) / fdu;
    gw[k + 32] = 0.5f * __logf(fdv) / fdv;
    __syncwarp();

    // X = sum_p g_p w_p w_p^T ; lane k emits columns k and k+32, in
    // 16-wide row quarters to keep peak register pressure under the cap.
#pragma unroll
    for (int half = 0; half < 2; ++half) {
        const int col = k + 32 * half;
#pragma unroll
        for (int q = 0; q < 2; ++q) {
            u64 acc[16];
#pragma unroll
            for (int j = 0; j < 16; ++j) acc[j] = 0ull;
            for (int p = 0; p < 64; ++p) {
                float sp = gw[p] * W[p][col];
                u64 sp2 = pk2(sp, sp);
                const u64* row = (const u64*)&W[p][0] + 16 * q;
#pragma unroll
                for (int j = 0; j < 16; ++j) acc[j] = fma2(sp2, row[j], acc[j]);
            }
#pragma unroll
            for (int j = 0; j < 16; ++j) {
                Xm[(32 * q + 2 * j) * 64 + col]     = lo2(acc[j]);
                Xm[(32 * q + 2 * j + 1) * 64 + col] = hi2(acc[j]);
            }
        }
    }
}

extern "C" void kernel_launch(void* const* d_in, const int* in_sizes, int n_in,
                              void* d_out, int out_size) {
    const float* P = (const float*)d_in[0];
    float* X = (float*)d_out;
    int nmat = in_sizes[0] / 4096;
    logeig_jacobi<<<nmat, 32>>>(P, X, nmat);
}

// round 10
// speedup vs baseline: 1.1690x; 1.1690x over previous
#include <cuda_runtime.h>
#include <math.h>

#define FULL 0xFFFFFFFFu
typedef unsigned long long u64;

// ---- packed f32x2 helpers (sm_103a) ------------------------------------
__device__ __forceinline__ u64 pk2(float lo, float hi) {
    u64 r; asm("mov.b64 %0, {%1, %2};" : "=l"(r) : "f"(lo), "f"(hi)); return r;
}
__device__ __forceinline__ float lo2(u64 x) { return __uint_as_float((unsigned)x); }
__device__ __forceinline__ float hi2(u64 x) { return __uint_as_float((unsigned)(x >> 32)); }
__device__ __forceinline__ u64 fma2(u64 a, u64 b, u64 c) {
    u64 d; asm("fma.rn.f32x2 %0, %1, %2, %3;" : "=l"(d) : "l"(a), "l"(b), "l"(c)); return d;
}
__device__ __forceinline__ u64 mul2(u64 a, u64 b) {
    u64 d; asm("mul.rn.f32x2 %0, %1, %2;" : "=l"(d) : "l"(a), "l"(b)); return d;
}
__device__ __forceinline__ u64 add2(u64 a, u64 b) {
    u64 d; asm("add.rn.f32x2 %0, %1, %2;" : "=l"(d) : "l"(a), "l"(b)); return d;
}
__device__ __forceinline__ u64 shfl64(u64 x, int src) {
    unsigned lo = (unsigned)x, hi = (unsigned)(x >> 32);
    lo = __shfl_sync(FULL, lo, src);
    hi = __shfl_sync(FULL, hi, src);
    return ((u64)hi << 32) | (u64)lo;
}
__device__ __forceinline__ u64 shfl64x(u64 x, int mask) {
    unsigned lo = (unsigned)x, hi = (unsigned)(x >> 32);
    lo = __shfl_xor_sync(FULL, lo, mask);
    hi = __shfl_xor_sync(FULL, hi, mask);
    return ((u64)hi << 32) | (u64)lo;
}
__device__ __forceinline__ float red2(u64 a, u64 b, u64 c, u64 d) {
    u64 s = add2(add2(a, b), add2(c, d));
    return lo2(s) + hi2(s);
}

// One warp per 64x64 SPD matrix. Lane k holds two columns (u, v) packed as
// 32 x f32x2. One-sided Jacobi, recursive-halving tournament, SHFL ring
// exchange (shared-memory exchange measured WORSE: crossbar is BW-bound at
// 128B/cyc; STS+LDS doubles traffic -> 26% regression in R9).
// FAST ROTATIONS: true column = gamma * stored. Update U' = U - t~u*V,
// V' = V + t~v*U (2 fma2/j instead of 4); gamma' = c*gamma. Norms du/dv
// tracked in TRUE space. Renormalize (x gamma) at every level end: drift
// bounded to <=32 rounds (gamma >= 0.707^32 ~ 1.5e-5, safe in fp32).
// Sweeps 0-5 ballot-free; 6+ ballot-gated skip rounds + early exit.
// Cap 16 sweeps (10 measured insufficient: rel_err 0.099).
// __launch_bounds__(32,12); (32,13) measured catastrophic (spills, 4x).
__global__ __launch_bounds__(32, 12) void logeig_jacobi(const float* __restrict__ P,
                                                        float* __restrict__ X,
                                                        int nmat) {
    const int m = blockIdx.x;
    if (m >= nmat) return;
    const int k = threadIdx.x;
    const float* __restrict__ Pm = P + (size_t)m * 4096;
    float* __restrict__ Xm = X + (size_t)m * 4096;

    u64 U[32], V[32];
#pragma unroll
    for (int j = 0; j < 32; ++j) {
        U[j] = pk2(Pm[(2 * j) * 64 + k],        Pm[(2 * j + 1) * 64 + k]);
        V[j] = pk2(Pm[(2 * j) * 64 + (k + 32)], Pm[(2 * j + 1) * 64 + (k + 32)]);
    }

    float du = 0.f, dv = 0.f;

    for (int sweep = 0; sweep < 16; ++sweep) {
        const bool gated = (sweep >= 6);

        // exact norms at sweep start (columns are true: renormed at level ends)
        {
            u64 a0 = 0, a1 = 0, b0 = 0, b1 = 0;
#pragma unroll
            for (int j = 0; j < 32; j += 2) {
                a0 = fma2(U[j], U[j], a0);     a1 = fma2(U[j + 1], U[j + 1], a1);
                b0 = fma2(V[j], V[j], b0);     b1 = fma2(V[j + 1], V[j + 1], b1);
            }
            u64 a = add2(a0, a1), b = add2(b0, b1);
            du = lo2(a) + hi2(a);
            dv = lo2(b) + hi2(b);
        }

        unsigned any = 0u;
        for (int g = 32; g >= 1; g >>= 1) {
            const int src = (k & ~(g - 1)) | ((k + 1) & (g - 1));

            float gu = 1.f, gv = 1.f, igu = 1.f, igv = 1.f;  // deferred scales

            // fresh dot at level start (gamma = 1: stored == true)
            float xt;
            {
                u64 x0 = 0, x1 = 0, x2 = 0, x3 = 0;
#pragma unroll
                for (int j = 0; j < 32; j += 4) {
                    x0 = fma2(U[j],     V[j],     x0);
                    x1 = fma2(U[j + 1], V[j + 1], x1);
                    x2 = fma2(U[j + 2], V[j + 2], x2);
                    x3 = fma2(U[j + 3], V[j + 3], x3);
                }
                xt = red2(x0, x1, x2, x3);
            }

            for (int r = 0; r < g; ++r) {
                bool rot = (xt * xt > 1e-8f * du * dv);
                unsigned bal;
                if (gated) {
                    bal = __ballot_sync(FULL, rot);
                    any |= bal;
                } else {
                    bal = FULL;
                }

                u64 x0 = 0, x1 = 0, x2 = 0, x3 = 0;
                if (bal) {
                    // one-division angle in TRUE space
                    float a = dv - du;
                    float b = 2.0f * xt;
                    float D = sqrtf(fmaf(a, a, b * b));
                    float t = __fdividef(b, a + copysignf(D, a));
                    if (!rot) t = 0.0f;
                    float w    = fmaf(t, t, 1.0f);
                    float c    = rsqrtf(w);
                    float invc = w * c;                     // 1/c

                    float tu = t * gv * igu;                // t * gv/gu
                    float tv = t * gu * igv;                // t * gu/gv
                    float ngu = c * gu,  nigu = invc * igu;
                    float ngv = c * gv,  nigv = invc * igv;
                    float ndu = fmaf(-t, xt, du);
                    float ndv = fmaf( t, xt, dv);

                    u64 ntu2 = pk2(-tu, -tu), tv2 = pk2(tv, tv);
#pragma unroll
                    for (int j = 0; j < 32; ++j) {
                        u64 un = fma2(ntu2, V[j], U[j]);    // U - tu*V
                        u64 vn = fma2(tv2,  U[j], V[j]);    // V + tv*U
                        U[j] = un;
                        V[j] = shfl64(vn, src);
                        if ((j & 3) == 0)      x0 = fma2(un, V[j], x0);
                        else if ((j & 3) == 1) x1 = fma2(un, V[j], x1);
                        else if ((j & 3) == 2) x2 = fma2(un, V[j], x2);
                        else                   x3 = fma2(un, V[j], x3);
                    }
                    du = ndu; gu = ngu; igu = nigu;
                    dv  = __shfl_sync(FULL, ndv,  src);
                    gv  = __shfl_sync(FULL, ngv,  src);
                    igv = __shfl_sync(FULL, nigv, src);
                } else {
                    // skip path: advance pairing + dot only
#pragma unroll
                    for (int j = 0; j < 32; ++j) {
                        V[j] = shfl64(V[j], src);
                        if ((j & 3) == 0)      x0 = fma2(U[j], V[j], x0);
                        else if ((j & 3) == 1) x1 = fma2(U[j], V[j], x1);
                        else if ((j & 3) == 2) x2 = fma2(U[j], V[j], x2);
                        else                   x3 = fma2(U[j], V[j], x3);
                    }
                    dv  = __shfl_sync(FULL, dv,  src);
                    gv  = __shfl_sync(FULL, gv,  src);
                    igv = __shfl_sync(FULL, igv, src);
                }
                float xs = red2(x0, x1, x2, x3);
                xt = xs * gu * gv;                          // true-space dot
            }

            // renormalize: fold gamma back into the stored columns
            {
                u64 gu2 = pk2(gu, gu), gv2 = pk2(gv, gv);
#pragma unroll
                for (int j = 0; j < 32; ++j) {
                    U[j] = mul2(U[j], gu2);
                    V[j] = mul2(V[j], gv2);
                }
            }

            // split: lower half-lanes keep u-set, upper keep v-set
            if (g > 1) {
                const int h = g >> 1;
                const bool low = (k & h) == 0;
#pragma unroll
                for (int j = 0; j < 32; ++j) {
                    u64 pu = shfl64x(U[j], h);
                    u64 pv = shfl64x(V[j], h);
                    if (low) V[j] = pu; else U[j] = pv;
                }
                float pdu = __shfl_xor_sync(FULL, du, h);
                float pdv = __shfl_xor_sync(FULL, dv, h);
                if (low) dv = pdu; else du = pdv;
            }
        }
        if (gated && any == 0u) break;
    }

    // exact final norms -> log weights  g_p = 0.5*log(d_p)/d_p
    float fdu, fdv;
    {
        u64 a0 = 0, a1 = 0, b0 = 0, b1 = 0;
#pragma unroll
        for (int j = 0; j < 32; j += 2) {
            a0 = fma2(U[j], U[j], a0);     a1 = fma2(U[j + 1], U[j + 1], a1);
            b0 = fma2(V[j], V[j], b0);     b1 = fma2(V[j + 1], V[j + 1], b1);
        }
        u64 a = add2(a0, a1), b = add2(b0, b1);
        fdu = lo2(a) + hi2(a);
        fdv = lo2(b) + hi2(b);
    }

    __shared__ __align__(16) float W[64][66];
    __shared__ float gw[64];
#pragma unroll
    for (int j = 0; j < 32; ++j) {
        W[k][2 * j]          = lo2(U[j]);
        W[k][2 * j + 1]      = hi2(U[j]);
        W[k + 32][2 * j]     = lo2(V[j]);
        W[k + 32][2 * j + 1] = hi2(V[j]);
    }
    gw[k]      = 0.5f * __logf(fdu) / fdu;
    gw[k + 32] = 0.5f * __logf(fdv) / fdv;
    __syncwarp();

    // X = sum_p g_p w_p w_p^T ; lane k emits columns k and k+32, in
    // 16-wide row quarters to keep peak register pressure under the cap.
#pragma unroll
    for (int half = 0; half < 2; ++half) {
        const int col = k + 32 * half;
#pragma unroll
        for (int q = 0; q < 2; ++q) {
            u64 acc[16];
#pragma unroll
            for (int j = 0; j < 16; ++j) acc[j] = 0ull;
            for (int p = 0; p < 64; ++p) {
                float sp = gw[p] * W[p][col];
                u64 sp2 = pk2(sp, sp);
                const u64* row = (const u64*)&W[p][0] + 16 * q;
#pragma unroll
                for (int j = 0; j < 16; ++j) acc[j] = fma2(sp2, row[j], acc[j]);
            }
#pragma unroll
            for (int j = 0; j < 16; ++j) {
                Xm[(32 * q + 2 * j) * 64 + col]     = lo2(acc[j]);
                Xm[(32 * q + 2 * j + 1) * 64 + col] = hi2(acc[j]);
            }
        }
    }
}

extern "C" void kernel_launch(void* const* d_in, const int* in_sizes, int n_in,
                              void* d_out, int out_size) {
    const float* P = (const float*)d_in[0];
    float* X = (float*)d_out;
    int nmat = in_sizes[0] / 4096;
    logeig_jacobi<<<nmat, 32>>>(P, X, nmat);
}

// round 11
// speedup vs baseline: 1.2047x; 1.0305x over previous
#include <cuda_runtime.h>
#include <math.h>

#define FULL 0xFFFFFFFFu
typedef unsigned long long u64;

// ---- packed f32x2 helpers (sm_103a) ------------------------------------
__device__ __forceinline__ u64 pk2(float lo, float hi) {
    u64 r; asm("mov.b64 %0, {%1, %2};" : "=l"(r) : "f"(lo), "f"(hi)); return r;
}
__device__ __forceinline__ float lo2(u64 x) { return __uint_as_float((unsigned)x); }
__device__ __forceinline__ float hi2(u64 x) { return __uint_as_float((unsigned)(x >> 32)); }
__device__ __forceinline__ u64 fma2(u64 a, u64 b, u64 c) {
    u64 d; asm("fma.rn.f32x2 %0, %1, %2, %3;" : "=l"(d) : "l"(a), "l"(b), "l"(c)); return d;
}
__device__ __forceinline__ u64 mul2(u64 a, u64 b) {
    u64 d; asm("mul.rn.f32x2 %0, %1, %2;" : "=l"(d) : "l"(a), "l"(b)); return d;
}
__device__ __forceinline__ u64 add2(u64 a, u64 b) {
    u64 d; asm("add.rn.f32x2 %0, %1, %2;" : "=l"(d) : "l"(a), "l"(b)); return d;
}
__device__ __forceinline__ u64 shfl64(u64 x, int src) {
    unsigned lo = (unsigned)x, hi = (unsigned)(x >> 32);
    lo = __shfl_sync(FULL, lo, src);
    hi = __shfl_sync(FULL, hi, src);
    return ((u64)hi << 32) | (u64)lo;
}
__device__ __forceinline__ u64 shfl64x(u64 x, int mask) {
    unsigned lo = (unsigned)x, hi = (unsigned)(x >> 32);
    lo = __shfl_xor_sync(FULL, lo, mask);
    hi = __shfl_xor_sync(FULL, hi, mask);
    return ((u64)hi << 32) | (u64)lo;
}
__device__ __forceinline__ float red2(u64 a, u64 b, u64 c, u64 d) {
    u64 s = add2(add2(a, b), add2(c, d));
    return lo2(s) + hi2(s);
}

// One warp per 64x64 SPD matrix. Lane k holds two columns (u, v) packed as
// 32 x f32x2. One-sided Jacobi, recursive-halving tournament, SHFL ring
// exchange (shared-memory exchange measured worse: crossbar BW-bound,
// R9 -26%). FAST ROTATIONS (true column = gamma * stored; rotation is
// 2 fma2/j instead of 4), with the exchange + next-pairing dot UNIFIED
// into one always-executed block: R10 duplicated it per branch and the
// extra live ranges spilled (L2 8.8%, alu +15%); R9's unified structure
// held 168 regs spill-free. Norms du/dv tracked in TRUE space; columns
// renormalized at level ends (<=32 rounds of drift, gamma >= 0.707^32).
// Sweeps 0-5 ballot-free; 6+ ballot-gated skip + sweep early exit.
// Cap 16 sweeps (10 measured insufficient: 0.099). (32,12) bounds:
// (32,13) measured catastrophic (spills, 4x).
__global__ __launch_bounds__(32, 12) void logeig_jacobi(const float* __restrict__ P,
                                                        float* __restrict__ X,
                                                        int nmat) {
    const int m = blockIdx.x;
    if (m >= nmat) return;
    const int k = threadIdx.x;
    const float* __restrict__ Pm = P + (size_t)m * 4096;
    float* __restrict__ Xm = X + (size_t)m * 4096;

    u64 U[32], V[32];
#pragma unroll
    for (int j = 0; j < 32; ++j) {
        U[j] = pk2(Pm[(2 * j) * 64 + k],        Pm[(2 * j + 1) * 64 + k]);
        V[j] = pk2(Pm[(2 * j) * 64 + (k + 32)], Pm[(2 * j + 1) * 64 + (k + 32)]);
    }

    float du = 0.f, dv = 0.f;

    for (int sweep = 0; sweep < 16; ++sweep) {
        const bool gated = (sweep >= 6);

        // exact true norms at sweep start (columns renormed at level ends)
        {
            u64 a0 = 0, a1 = 0, b0 = 0, b1 = 0;
#pragma unroll
            for (int j = 0; j < 32; j += 2) {
                a0 = fma2(U[j], U[j], a0);     a1 = fma2(U[j + 1], U[j + 1], a1);
                b0 = fma2(V[j], V[j], b0);     b1 = fma2(V[j + 1], V[j + 1], b1);
            }
            u64 a = add2(a0, a1), b = add2(b0, b1);
            du = lo2(a) + hi2(a);
            dv = lo2(b) + hi2(b);
        }

        unsigned any = 0u;
        for (int g = 32; g >= 1; g >>= 1) {
            const int src = (k & ~(g - 1)) | ((k + 1) & (g - 1));

            float gu = 1.f, gv = 1.f, igu = 1.f, igv = 1.f;

            // fresh dot at level start (gamma = 1: stored == true)
            float xt;
            {
                u64 x0 = 0, x1 = 0, x2 = 0, x3 = 0;
#pragma unroll
                for (int j = 0; j < 32; j += 4) {
                    x0 = fma2(U[j],     V[j],     x0);
                    x1 = fma2(U[j + 1], V[j + 1], x1);
                    x2 = fma2(U[j + 2], V[j + 2], x2);
                    x3 = fma2(U[j + 3], V[j + 3], x3);
                }
                xt = red2(x0, x1, x2, x3);
            }

            for (int r = 0; r < g; ++r) {
                bool rot = (xt * xt > 1e-8f * du * dv);
                unsigned bal;
                if (gated) {
                    bal = __ballot_sync(FULL, rot);
                    any |= bal;
                } else {
                    bal = FULL;
                }

                if (bal) {
                    // one-division angle in TRUE space
                    float a = dv - du;
                    float b = 2.0f * xt;
                    float D = sqrtf(fmaf(a, a, b * b));
                    float t = __fdividef(b, a + copysignf(D, a));
                    if (!rot) t = 0.0f;
                    float w    = fmaf(t, t, 1.0f);
                    float c    = rsqrtf(w);
                    float invc = w * c;                     // 1/c

                    float tu = t * gv * igu;                // t * gv/gu
                    float tv = t * gu * igv;                // t * gu/gv
                    gu *= c;  igu *= invc;
                    du  = fmaf(-t, xt, du);
                    dv  = fmaf( t, xt, dv);

                    u64 ntu2 = pk2(-tu, -tu), tv2 = pk2(tv, tv);
#pragma unroll
                    for (int j = 0; j < 32; ++j) {
                        u64 un = fma2(ntu2, V[j], U[j]);    // U - tu*V
                        u64 vn = fma2(tv2,  U[j], V[j]);    // V + tv*U
                        U[j] = un;
                        V[j] = vn;
                    }
                    gv *= c;  igv *= invc;
                }

                // unified exchange + fused next-pairing dot (both paths)
                {
                    u64 x0 = 0, x1 = 0, x2 = 0, x3 = 0;
#pragma unroll
                    for (int j = 0; j < 32; ++j) {
                        V[j] = shfl64(V[j], src);
                        if ((j & 3) == 0)      x0 = fma2(U[j], V[j], x0);
                        else if ((j & 3) == 1) x1 = fma2(U[j], V[j], x1);
                        else if ((j & 3) == 2) x2 = fma2(U[j], V[j], x2);
                        else                   x3 = fma2(U[j], V[j], x3);
                    }
                    dv  = __shfl_sync(FULL, dv,  src);
                    gv  = __shfl_sync(FULL, gv,  src);
                    igv = __shfl_sync(FULL, igv, src);
                    float xs = red2(x0, x1, x2, x3);
                    xt = xs * gu * gv;                      // true-space dot
                }
            }

            // renormalize: fold gamma back into the stored columns
            {
                u64 gu2 = pk2(gu, gu), gv2 = pk2(gv, gv);
#pragma unroll
                for (int j = 0; j < 32; ++j) {
                    U[j] = mul2(U[j], gu2);
                    V[j] = mul2(V[j], gv2);
                }
            }

            // split: lower half-lanes keep u-set, upper keep v-set
            if (g > 1) {
                const int h = g >> 1;
                const bool low = (k & h) == 0;
#pragma unroll
                for (int j = 0; j < 32; ++j) {
                    u64 pu = shfl64x(U[j], h);
                    u64 pv = shfl64x(V[j], h);
                    if (low) V[j] = pu; else U[j] = pv;
                }
                float pdu = __shfl_xor_sync(FULL, du, h);
                float pdv = __shfl_xor_sync(FULL, dv, h);
                if (low) dv = pdu; else du = pdv;
            }
        }
        if (gated && any == 0u) break;
    }

    // exact final norms -> log weights  g_p = 0.5*log(d_p)/d_p
    float fdu, fdv;
    {
        u64 a0 = 0, a1 = 0, b0 = 0, b1 = 0;
#pragma unroll
        for (int j = 0; j < 32; j += 2) {
            a0 = fma2(U[j], U[j], a0);     a1 = fma2(U[j + 1], U[j + 1], a1);
            b0 = fma2(V[j], V[j], b0);     b1 = fma2(V[j + 1], V[j + 1], b1);
        }
        u64 a = add2(a0, a1), b = add2(b0, b1);
        fdu = lo2(a) + hi2(a);
        fdv = lo2(b) + hi2(b);
    }

    __shared__ __align__(16) float W[64][66];
    __shared__ float gw[64];
#pragma unroll
    for (int j = 0; j < 32; ++j) {
        W[k][2 * j]          = lo2(U[j]);
        W[k][2 * j + 1]      = hi2(U[j]);
        W[k + 32][2 * j]     = lo2(V[j]);
        W[k + 32][2 * j + 1] = hi2(V[j]);
    }
    gw[k]      = 0.5f * __logf(fdu) / fdu;
    gw[k + 32] = 0.5f * __logf(fdv) / fdv;
    __syncwarp();

    // X = sum_p g_p w_p w_p^T ; lane k emits columns k and k+32, in
    // 16-wide row quarters to keep peak register pressure under the cap.
#pragma unroll
    for (int half = 0; half < 2; ++half) {
        const int col = k + 32 * half;
#pragma unroll
        for (int q = 0; q < 2; ++q) {
            u64 acc[16];
#pragma unroll
            for (int j = 0; j < 16; ++j) acc[j] = 0ull;
            for (int p = 0; p < 64; ++p) {
                float sp = gw[p] * W[p][col];
                u64 sp2 = pk2(sp, sp);
                const u64* row = (const u64*)&W[p][0] + 16 * q;
#pragma unroll
                for (int j = 0; j < 16; ++j) acc[j] = fma2(sp2, row[j], acc[j]);
            }
#pragma unroll
            for (int j = 0; j < 16; ++j) {
                Xm[(32 * q + 2 * j) * 64 + col]     = lo2(acc[j]);
                Xm[(32 * q + 2 * j + 1) * 64 + col] = hi2(acc[j]);
            }
        }
    }
}

extern "C" void kernel_launch(void* const* d_in, const int* in_sizes, int n_in,
                              void* d_out, int out_size) {
    const float* P = (const float*)d_in[0];
    float* X = (float*)d_out;
    int nmat = in_sizes[0] / 4096;
    logeig_jacobi<<<nmat, 32>>>(P, X, nmat);
}

// round 12
// speedup vs baseline: 1.2641x; 1.0493x over previous
#include <cuda_runtime.h>
#include <math.h>

#define FULL 0xFFFFFFFFu
typedef unsigned long long u64;

// ---- packed f32x2 helpers (sm_103a) ------------------------------------
__device__ __forceinline__ u64 pk2(float lo, float hi) {
    u64 r; asm("mov.b64 %0, {%1, %2};" : "=l"(r) : "f"(lo), "f"(hi)); return r;
}
__device__ __forceinline__ float lo2(u64 x) { return __uint_as_float((unsigned)x); }
__device__ __forceinline__ float hi2(u64 x) { return __uint_as_float((unsigned)(x >> 32)); }
__device__ __forceinline__ u64 fma2(u64 a, u64 b, u64 c) {
    u64 d; asm("fma.rn.f32x2 %0, %1, %2, %3;" : "=l"(d) : "l"(a), "l"(b), "l"(c)); return d;
}
__device__ __forceinline__ u64 mul2(u64 a, u64 b) {
    u64 d; asm("mul.rn.f32x2 %0, %1, %2;" : "=l"(d) : "l"(a), "l"(b)); return d;
}
__device__ __forceinline__ u64 add2(u64 a, u64 b) {
    u64 d; asm("add.rn.f32x2 %0, %1, %2;" : "=l"(d) : "l"(a), "l"(b)); return d;
}
__device__ __forceinline__ u64 shfl64(u64 x, int src) {
    unsigned lo = (unsigned)x, hi = (unsigned)(x >> 32);
    lo = __shfl_sync(FULL, lo, src);
    hi = __shfl_sync(FULL, hi, src);
    return ((u64)hi << 32) | (u64)lo;
}
__device__ __forceinline__ u64 shfl64x(u64 x, int mask) {
    unsigned lo = (unsigned)x, hi = (unsigned)(x >> 32);
    lo = __shfl_xor_sync(FULL, lo, mask);
    hi = __shfl_xor_sync(FULL, hi, mask);
    return ((u64)hi << 32) | (u64)lo;
}
__device__ __forceinline__ float red2(u64 a, u64 b, u64 c, u64 d) {
    u64 s = add2(add2(a, b), add2(c, d));
    return lo2(s) + hi2(s);
}

// One warp per 64x64 SPD matrix. Lane k holds two columns (u, v) packed as
// 32 x f32x2. One-sided Jacobi, recursive-halving tournament, SHFL ring
// exchange, fused next-pairing dot, standard (c,s) rotations.
// Design decisions locked by measurement:
//  - SHFL exchange (shared-mem STS/LDS.128 doubles crossbar traffic: -26%, R9)
//  - standard rotations (fast/deferred-scale rotations trade fma for scalar
//    ALU on the critical path: -5% (R11) or spills (R10))
//  - (32,12) launch bounds ((32,13) spills U/V: 4x slowdown, R7)
//  - cap 16 sweeps (cap 10 diverges: rel_err 0.099, R4)
//  - threshold 2e-8; measured err ~ sqrt(thr): 1e-10->3.2e-5, 1e-9->9.9e-5,
//    1e-8->3.28e-4 => expect ~4.6e-4 (gate 1e-3)
//  - ballot-gated skip rounds + sweep early-exit from sweep 4
__global__ __launch_bounds__(32, 12) void logeig_jacobi(const float* __restrict__ P,
                                                        float* __restrict__ X,
                                                        int nmat) {
    const int m = blockIdx.x;
    if (m >= nmat) return;
    const int k = threadIdx.x;
    const float* __restrict__ Pm = P + (size_t)m * 4096;
    float* __restrict__ Xm = X + (size_t)m * 4096;

    u64 U[32], V[32];
#pragma unroll
    for (int j = 0; j < 32; ++j) {
        U[j] = pk2(Pm[(2 * j) * 64 + k],        Pm[(2 * j + 1) * 64 + k]);
        V[j] = pk2(Pm[(2 * j) * 64 + (k + 32)], Pm[(2 * j + 1) * 64 + (k + 32)]);
    }

    float du = 0.f, dv = 0.f;

    for (int sweep = 0; sweep < 16; ++sweep) {
        const bool gated = (sweep >= 4);

        // exact norms at sweep start
        {
            u64 a0 = 0, a1 = 0, b0 = 0, b1 = 0;
#pragma unroll
            for (int j = 0; j < 32; j += 2) {
                a0 = fma2(U[j], U[j], a0);     a1 = fma2(U[j + 1], U[j + 1], a1);
                b0 = fma2(V[j], V[j], b0);     b1 = fma2(V[j + 1], V[j + 1], b1);
            }
            u64 a = add2(a0, a1), b = add2(b0, b1);
            du = lo2(a) + hi2(a);
            dv = lo2(b) + hi2(b);
        }

        unsigned any = 0u;
        for (int g = 32; g >= 1; g >>= 1) {
            const int src = (k & ~(g - 1)) | ((k + 1) & (g - 1));

            // fresh dot at level start
            float x;
            {
                u64 x0 = 0, x1 = 0, x2 = 0, x3 = 0;
#pragma unroll
                for (int j = 0; j < 32; j += 4) {
                    x0 = fma2(U[j],     V[j],     x0);
                    x1 = fma2(U[j + 1], V[j + 1], x1);
                    x2 = fma2(U[j + 2], V[j + 2], x2);
                    x3 = fma2(U[j + 3], V[j + 3], x3);
                }
                x = red2(x0, x1, x2, x3);
            }

            for (int r = 0; r < g; ++r) {
                bool rot = (x * x > 2e-8f * du * dv);
                unsigned bal;
                if (gated) {
                    bal = __ballot_sync(FULL, rot);
                    any |= bal;
                } else {
                    bal = FULL;
                }

                u64 x0 = 0, x1 = 0, x2 = 0, x3 = 0;
                if (bal) {
                    // full path: one-division angle, rotate, fused next dot
                    float a = dv - du;
                    float b = 2.0f * x;
                    float D = sqrtf(fmaf(a, a, b * b));
                    float t = __fdividef(b, a + copysignf(D, a));
                    if (!rot) t = 0.0f;                   // c=1, s=0 fallthrough
                    float c = rsqrtf(fmaf(t, t, 1.0f));
                    float s = t * c;

                    float ndu = fmaf(-t, x, du);
                    float ndv = fmaf( t, x, dv);

                    u64 cc = pk2(c, c), ss = pk2(s, s), ns = pk2(-s, -s);
#pragma unroll
                    for (int j = 0; j < 32; ++j) {
                        u64 un = fma2(cc, U[j], mul2(ns, V[j]));
                        u64 vn = fma2(cc, V[j], mul2(ss, U[j]));
                        U[j] = un;
                        V[j] = shfl64(vn, src);
                        if ((j & 3) == 0)      x0 = fma2(un, V[j], x0);
                        else if ((j & 3) == 1) x1 = fma2(un, V[j], x1);
                        else if ((j & 3) == 2) x2 = fma2(un, V[j], x2);
                        else                   x3 = fma2(un, V[j], x3);
                    }
                    du = ndu;
                    dv = __shfl_sync(FULL, ndv, src);
                } else {
                    // skip path: no lane rotates -> advance pairing + dot only
#pragma unroll
                    for (int j = 0; j < 32; ++j) {
                        V[j] = shfl64(V[j], src);
                        if ((j & 3) == 0)      x0 = fma2(U[j], V[j], x0);
                        else if ((j & 3) == 1) x1 = fma2(U[j], V[j], x1);
                        else if ((j & 3) == 2) x2 = fma2(U[j], V[j], x2);
                        else                   x3 = fma2(U[j], V[j], x3);
                    }
                    dv = __shfl_sync(FULL, dv, src);
                }
                x = red2(x0, x1, x2, x3);
            }

            // split: lower half-lanes keep u-set, upper keep v-set
            if (g > 1) {
                const int h = g >> 1;
                const bool low = (k & h) == 0;
#pragma unroll
                for (int j = 0; j < 32; ++j) {
                    u64 pu = shfl64x(U[j], h);
                    u64 pv = shfl64x(V[j], h);
                    if (low) V[j] = pu; else U[j] = pv;
                }
                float pdu = __shfl_xor_sync(FULL, du, h);
                float pdv = __shfl_xor_sync(FULL, dv, h);
                if (low) dv = pdu; else du = pdv;
            }
        }
        if (gated && any == 0u) break;
    }

    // exact final norms -> log weights  g_p = 0.5*log(d_p)/d_p
    float fdu, fdv;
    {
        u64 a0 = 0, a1 = 0, b0 = 0, b1 = 0;
#pragma unroll
        for (int j = 0; j < 32; j += 2) {
            a0 = fma2(U[j], U[j], a0);     a1 = fma2(U[j + 1], U[j + 1], a1);
            b0 = fma2(V[j], V[j], b0);     b1 = fma2(V[j + 1], V[j + 1], b1);
        }
        u64 a = add2(a0, a1), b = add2(b0, b1);
        fdu = lo2(a) + hi2(a);
        fdv = lo2(b) + hi2(b);
    }

    __shared__ __align__(16) float W[64][66];
    __shared__ float gw[64];
#pragma unroll
    for (int j = 0; j < 32; ++j) {
        W[k][2 * j]          = lo2(U[j]);
        W[k][2 * j + 1]      = hi2(U[j]);
        W[k + 32][2 * j]     = lo2(V[j]);
        W[k + 32][2 * j + 1] = hi2(V[j]);
    }
    gw[k]      = 0.5f * __logf(fdu) / fdu;
    gw[k + 32] = 0.5f * __logf(fdv) / fdv;
    __syncwarp();

    // X = sum_p g_p w_p w_p^T ; lane k emits columns k and k+32, in
    // 16-wide row quarters to keep peak register pressure under the cap.
#pragma unroll
    for (int half = 0; half < 2; ++half) {
        const int col = k + 32 * half;
#pragma unroll
        for (int q = 0; q < 2; ++q) {
            u64 acc[16];
#pragma unroll
            for (int j = 0; j < 16; ++j) acc[j] = 0ull;
            for (int p = 0; p < 64; ++p) {
                float sp = gw[p] * W[p][col];
                u64 sp2 = pk2(sp, sp);
                const u64* row = (const u64*)&W[p][0] + 16 * q;
#pragma unroll
                for (int j = 0; j < 16; ++j) acc[j] = fma2(sp2, row[j], acc[j]);
            }
#pragma unroll
            for (int j = 0; j < 16; ++j) {
                Xm[(32 * q + 2 * j) * 64 + col]     = lo2(acc[j]);
                Xm[(32 * q + 2 * j + 1) * 64 + col] = hi2(acc[j]);
            }
        }
    }
}

extern "C" void kernel_launch(void* const* d_in, const int* in_sizes, int n_in,
                              void* d_out, int out_size) {
    const float* P = (const float*)d_in[0];
    float* X = (float*)d_out;
    int nmat = in_sizes[0] / 4096;
    logeig_jacobi<<<nmat, 32>>>(P, X, nmat);
}